// round 15
// baseline (speedup 1.0000x reference)
#include <cuda_runtime.h>
#include <cuda_fp16.h>

// ---------------------------------------------------------------------------
// Conv_2259152798130 — fused e3nn edge conv.
// R15: R14 per-tile body (at HMMA dispatch floor) + persistent-CTA tile
// scheduler: grid = 4*148 CTAs, tiles fetched from a global atomic counter
// (near-perfect balance, no per-tile block launch/retire). Counter reset in
// final_kernel for graph-replay determinism.
// ---------------------------------------------------------------------------

#define NN       10000
#define OUT_DIM  80
#define NORM_V        0.14433756729740643f   // 1/sqrt(48)
#define INV_SQRT3_V   0.57735026918962576f
#define RSQRT32_V     0.17677669529663687f   // 1/sqrt(32)

// zero-initialized at module load; final_kernel restores zeros each run
__device__ float g_sums[NN * OUT_DIM];
__device__ float g_cnt[NN];
__device__ unsigned g_tile_ctr;              // persistent work queue
// W2 fp16: row j (out col) holds 64 k's as 32 half2 (128B rows)
__device__ unsigned g_w2h[2304 * 32];

// 72 blocks of (32,8): 32-col x 64-row W2 tiles via smem transpose.
__global__ void convert_w2(const float* __restrict__ w2) {
    __shared__ float s[64][33];
    const int x  = threadIdx.x;            // 0..31
    const int y  = threadIdx.y;            // 0..7
    const int j0 = blockIdx.x * 32;
#pragma unroll
    for (int r = 0; r < 8; r++) {          // coalesced 128B reads
        const int k = y * 8 + r;
        s[k][x] = w2[k * 2304 + j0 + x];
    }
    __syncthreads();
#pragma unroll
    for (int q = 0; q < 4; q++) {          // coalesced 128B writes (x = kp)
        const int jj = y * 4 + q;
        const __half2 h2 = __halves2half2(
            __float2half_rn(s[2 * x][jj]),
            __float2half_rn(s[2 * x + 1][jj]));
        g_w2h[(j0 + jj) * 32 + x] = *(const unsigned*)&h2;
    }
}

// mma m16n8k16 fp16 -> fp32 accum (A row-major, B col-major)
__device__ __forceinline__ void mma_f16(float c[4], const unsigned a[4],
                                        unsigned b0, unsigned b1) {
    asm volatile(
        "mma.sync.aligned.m16n8k16.row.col.f32.f16.f16.f32 "
        "{%0,%1,%2,%3}, {%4,%5,%6,%7}, {%8,%9}, {%0,%1,%2,%3};"
        : "+f"(c[0]), "+f"(c[1]), "+f"(c[2]), "+f"(c[3])
        : "r"(a[0]), "r"(a[1]), "r"(a[2]), "r"(a[3]), "r"(b0), "r"(b1));
}

__device__ __forceinline__ void ldsm_x4(unsigned& r0, unsigned& r1,
                                        unsigned& r2, unsigned& r3,
                                        unsigned addr) {
    asm volatile("ldmatrix.sync.aligned.m8n8.x4.shared.b16 {%0,%1,%2,%3}, [%4];"
                 : "=r"(r0), "=r"(r1), "=r"(r2), "=r"(r3) : "r"(addr));
}

// packed / scalar global reductions (no return)
__device__ __forceinline__ void red_add2(float* a, float x, float y) {
    asm volatile("red.global.add.v2.f32 [%0], {%1, %2};"
                 :: "l"(a), "f"(x), "f"(y) : "memory");
}
__device__ __forceinline__ void red_add1(float* a, float x) {
    asm volatile("red.global.add.f32 [%0], %1;"
                 :: "l"(a), "f"(x) : "memory");
}

__device__ __forceinline__ void cp_commit() {
    asm volatile("cp.async.commit_group;" ::: "memory");
}
template <int N>
__device__ __forceinline__ void cp_wait() {
    asm volatile("cp.async.wait_group %0;" :: "n"(N) : "memory");
}

// prefetch one W2 chunk: 64 rows x 128B, seg ^= (n&7) swizzle, + 64 b2 floats
__device__ __forceinline__ void prefetch_chunk(
    unsigned wbuf_b, float* bbuf, const float* __restrict__ b2,
    int ch, int tid)
{
#pragma unroll
    for (int t = 0; t < 4; t++) {
        const int i = tid + t * 128;       // 0..511
        const int n = i >> 3;              // row (out col) 0..63
        const int s = i & 7;               // 16B segment within row
        const unsigned dst = wbuf_b + (unsigned)(n * 128 + ((s ^ (n & 7)) << 4));
        const char* src = (const char*)g_w2h + (size_t)(ch * 64 + n) * 128 + s * 16;
        asm volatile("cp.async.cg.shared.global [%0], [%1], 16;"
                     :: "r"(dst), "l"(src));
    }
    if (tid < 16) {
        unsigned dst;
        asm("{ .reg .u64 t; cvta.to.shared.u64 t, %1; cvt.u32.u64 %0, t; }"
            : "=r"(dst) : "l"(bbuf + tid * 4));
        const float* src = b2 + ch * 64 + tid * 4;
        asm volatile("cp.async.cg.shared.global [%0], [%1], 16;"
                     :: "r"(dst), "l"(src));
    }
}

// ---------------------------------------------------------------------------
// Shared layout (4-byte units), 64 edges/tile, total 14148 = 56592 B
//   attrh [64][17] u32 @ 0      (attr fp16 pairs)
//   b1s   [64]         @ 1088
//   Wst   [3][2048]u32 @ 1152   (fp16 stages; buf0 = W1 during MLP1)
//   b2st  [3][64]      @ 7296
//   x0_s  [64][33]     @ 7488
//   y1_s  [64][17]     @ 9600
//   z1_s  [64][49]     @ 10688
//   sh0_s [64]         @ 13824
//   sh1_s [64][3]      @ 13888
//   dst_s [64] int     @ 14080
//   tile_s int         @ 14144
// ---------------------------------------------------------------------------
#define SMEM_BYTES (14148 * 4)

__global__ __launch_bounds__(128, 4) void edge_kernel(
    int E, int nTiles,
    const int*   __restrict__ dst,
    const float* __restrict__ x_src,
    const float* __restrict__ sh,
    const float* __restrict__ edge_attr,
    const float* __restrict__ w1,
    const float* __restrict__ b1,
    const float* __restrict__ b2)
{
    extern __shared__ float smem[];
    unsigned* attrh = (unsigned*)smem;
    float* b1s   = smem + 1088;
    float* b2st  = smem + 7296;
    float* x0_s  = smem + 7488;
    float* y1_s  = smem + 9600;
    float* z1_s  = smem + 10688;
    float* sh0_s = smem + 13824;
    float* sh1_s = smem + 13888;
    int*   dst_s = (int*)(smem + 14080);
    volatile int* tile_s = (volatile int*)(smem + 14144);

    unsigned wst_b;                        // byte smem addr of Wst
    asm("{ .reg .u64 t; cvta.to.shared.u64 t, %1; cvt.u32.u64 %0, t; }"
        : "=r"(wst_b) : "l"(smem + 1152));

    const int tid  = threadIdx.x;
    const int lane = tid & 31;
    const int warp = tid >> 5;          // 0..3 -> edges warp*16 .. +15
    const int gid  = lane >> 2;
    const int qd   = lane & 3;
    const int er0  = warp * 16 + gid;
    const int er1  = er0 + 8;
    const int lrow = lane & 7;
    const int lmat = lane >> 3;
    const unsigned lmoff0 = (unsigned)(lrow * 128 + (((lmat)     ^ lrow) << 4));
    const unsigned lmoff1 = (unsigned)(lrow * 128 + (((lmat | 4) ^ lrow) << 4));
    const int e    = tid & 63;
    const int half = tid >> 6;

    for (;;) {
        // ---- fetch next tile (also separates tiles: prior smem reads done,
        //      buf0 ldsm of previous tile's ch=35 retired) ----
        if (tid == 0) *tile_s = (int)atomicAdd(&g_tile_ctr, 1u);
        __syncthreads();
        const int tile = *tile_s;
        if (tile >= nTiles) break;

        const int eBase = tile * 64;
        const int ge    = eBase + e;
        const bool valid = (ge < E);

        // ---- kick off cp.async: chunk0 -> buf1, chunk1 -> buf2 ----
        prefetch_chunk(wst_b + 8192,  b2st + 64,  b2, 0, tid);   cp_commit();
        prefetch_chunk(wst_b + 16384, b2st + 128, b2, 1, tid);   cp_commit();

        // ---- stage W1 fp32 -> fp16 into Wst buf0 (ldmatrix layout) ----
        {
            const int nW = (tid & 31) | (((tid >> 5) & 1) << 5);  // n: 0..63
            const int pb = (tid >> 6) << 3;                       // 0 or 8
#pragma unroll
            for (int pp = 0; pp < 8; pp++) {
                const int p  = pb + pp;
                const float v0 = w1[(2 * p)     * 64 + nW];
                const float v1 = w1[(2 * p + 1) * 64 + nW];
                const __half2 h2 = __halves2half2(__float2half_rn(v0),
                                                  __float2half_rn(v1));
                const unsigned addr = wst_b +
                    (unsigned)(nW * 128 + (((p >> 2) ^ (nW & 7)) << 4) + (p & 3) * 4);
                asm volatile("st.shared.b32 [%0], %1;"
                             :: "r"(addr), "r"(*(const unsigned*)&h2));
            }
        }

        // ---- Phase 0: per-edge features + attr fp16 ----
        if (tid < 64) b1s[tid] = b1[tid];

        {
            const float* ap = edge_attr + (size_t)ge * 32 + half * 16;
#pragma unroll
            for (int q = 0; q < 4; q++) {
                float4 v = valid ? ((const float4*)ap)[q]
                                 : make_float4(0.f, 0.f, 0.f, 0.f);
                __half2 p0 = __halves2half2(__float2half_rn(v.x), __float2half_rn(v.y));
                __half2 p1 = __halves2half2(__float2half_rn(v.z), __float2half_rn(v.w));
                attrh[e * 17 + half * 8 + q * 2]     = *(const unsigned*)&p0;
                attrh[e * 17 + half * 8 + q * 2 + 1] = *(const unsigned*)&p1;
            }
        }

        if (half == 0) {   // one thread per edge
            dst_s[e] = valid ? dst[ge] : 0;
            float s0 = 0.f, s1 = 0.f, s2 = 0.f, s3 = 0.f;
            if (valid) {
                const float4 shv = *(const float4*)&sh[ge * 4];
                s0 = shv.x; s1 = shv.y; s2 = shv.z; s3 = shv.w;
            }
            sh0_s[e] = s0;
            sh1_s[e * 3 + 0] = s1; sh1_s[e * 3 + 1] = s2; sh1_s[e * 3 + 2] = s3;
#pragma unroll
            for (int q = 0; q < 8; q++) {
                float4 v = valid ? ((const float4*)&x_src[ge * 80])[q]
                                 : make_float4(0.f, 0.f, 0.f, 0.f);
                x0_s[e * 33 + q * 4 + 0] = v.x;
                x0_s[e * 33 + q * 4 + 1] = v.y;
                x0_s[e * 33 + q * 4 + 2] = v.z;
                x0_s[e * 33 + q * 4 + 3] = v.w;
            }
#pragma unroll
            for (int u = 0; u < 16; u++) {
                float a = 0.f, b = 0.f, c = 0.f;
                if (valid) {
                    a = x_src[ge * 80 + 32 + u * 3 + 0];
                    b = x_src[ge * 80 + 32 + u * 3 + 1];
                    c = x_src[ge * 80 + 32 + u * 3 + 2];
                }
                y1_s[e * 17 + u] = INV_SQRT3_V * (a * s1 + b * s2 + c * s3);
                z1_s[e * 49 + u * 3 + 0] = a * s0;
                z1_s[e * 49 + u * 3 + 1] = b * s0;
                z1_s[e * 49 + u * 3 + 2] = c * s0;
            }
        }

        __syncthreads();   // W1 STS + attrh + features visible

        // ---- MLP1 via mma: h fragments land directly in main-GEMM A regs ----
        unsigned a[4][4];
        {
            unsigned am[2][4];
            am[0][0] = attrh[er0 * 17 + qd];
            am[0][1] = attrh[er1 * 17 + qd];
            am[0][2] = attrh[er0 * 17 + 4 + qd];
            am[0][3] = attrh[er1 * 17 + 4 + qd];
            am[1][0] = attrh[er0 * 17 + 8 + qd];
            am[1][1] = attrh[er1 * 17 + 8 + qd];
            am[1][2] = attrh[er0 * 17 + 12 + qd];
            am[1][3] = attrh[er1 * 17 + 12 + qd];

#pragma unroll
            for (int t = 0; t < 8; t++) {
                float c[4];
                const float bb0 = b1s[t * 8 + 2 * qd];
                const float bb1 = b1s[t * 8 + 2 * qd + 1];
                c[0] = bb0; c[1] = bb1; c[2] = bb0; c[3] = bb1;
                unsigned b0, b1r, b2r, b3;
                ldsm_x4(b0, b1r, b2r, b3, wst_b + (unsigned)(t * 1024) + lmoff0);
                mma_f16(c, am[0], b0, b1r);
                mma_f16(c, am[1], b2r, b3);
                const __half2 plo = __halves2half2(
                    __float2half_rn(fmaxf(c[0], 0.f)), __float2half_rn(fmaxf(c[1], 0.f)));
                const __half2 phi = __halves2half2(
                    __float2half_rn(fmaxf(c[2], 0.f)), __float2half_rn(fmaxf(c[3], 0.f)));
                a[t >> 1][(t & 1) * 2 + 0] = *(const unsigned*)&plo;
                a[t >> 1][(t & 1) * 2 + 1] = *(const unsigned*)&phi;
            }
        }

        // accumulators
        float acc0[2][4][2];
        float cacc[2][2][2];
        float dacc[2][2][2][3];
#pragma unroll
        for (int r = 0; r < 2; r++) {
#pragma unroll
            for (int n = 0; n < 4; n++) { acc0[r][n][0] = 0.f; acc0[r][n][1] = 0.f; }
#pragma unroll
            for (int p = 0; p < 2; p++) {
                cacc[r][p][0] = 0.f; cacc[r][p][1] = 0.f;
#pragma unroll
                for (int j = 0; j < 2; j++) {
                    dacc[r][p][j][0] = 0.f; dacc[r][p][j][1] = 0.f; dacc[r][p][j][2] = 0.f;
                }
            }
        }

        // ---- main pipelined loop: chunk ch lives in buf (ch+1)%3 ----
#pragma unroll 1
        for (int ch = 0; ch < 36; ch++) {
            cp_wait<1>();      // chunk ch resident (own thread's view)
            __syncthreads();   // visible to all; buf ch%3 free (W1 dead at ch=0)
            if (ch + 2 < 36)
                prefetch_chunk(wst_b + (unsigned)((ch % 3) * 8192),
                               b2st + (ch % 3) * 64,
                               b2, ch + 2, tid);
            cp_commit();       // always commit to keep group cadence

            // ---- hoisted out1 writeout (overlaps region-B mma) ----
            if (ch == 28) {
#pragma unroll
                for (int r = 0; r < 2; r++) {
                    const int er = r ? er1 : er0;
                    if (eBase + er < E) {
                        const int node = dst_s[er];
                        const float s1v = sh1_s[er * 3 + 0];
                        const float s2v = sh1_s[er * 3 + 1];
                        const float s3v = sh1_s[er * 3 + 2];
#pragma unroll
                        for (int p = 0; p < 2; p++) {
                            const int v0 = p * 8 + 2 * qd;      // j = 0 (even v)
                            float* base0 = &g_sums[node * 80 + 32 + v0 * 3];
                            {
                                const float cc = cacc[r][p][0];
                                red_add2(base0,
                                         NORM_V * (s1v * cc + dacc[r][p][0][0]),
                                         NORM_V * (s2v * cc + dacc[r][p][0][1]));
                                red_add1(base0 + 2,
                                         NORM_V * (s3v * cc + dacc[r][p][0][2]));
                            }
                            {                                    // j = 1 (odd v)
                                const float cc = cacc[r][p][1];
                                red_add1(base0 + 3,
                                         NORM_V * (s1v * cc + dacc[r][p][1][0]));
                                red_add2(base0 + 4,
                                         NORM_V * (s2v * cc + dacc[r][p][1][1]),
                                         NORM_V * (s3v * cc + dacc[r][p][1][2]));
                            }
                        }
                    }
                }
            }

            const unsigned chunk_b = wst_b + (unsigned)(((ch + 1) % 3) * 8192);
            const float*   bb      = b2st + ((ch + 1) % 3) * 64;

#pragma unroll
            for (int h2 = 0; h2 < 2; h2++) {
                float c[4][4];
#pragma unroll
                for (int n = 0; n < 4; n++) {
                    const float bb0 = bb[(h2 * 4 + n) * 8 + 2 * qd];
                    const float bb1 = bb[(h2 * 4 + n) * 8 + 2 * qd + 1];
                    c[n][0] = bb0; c[n][1] = bb1; c[n][2] = bb0; c[n][3] = bb1;
                }
#pragma unroll
                for (int n = 0; n < 4; n++) {
                    const unsigned nb_base = chunk_b + (unsigned)((h2 * 4 + n) * 1024);
                    unsigned b0, b1r, b2r, b3, b4, b5, b6, b7;
                    ldsm_x4(b0, b1r, b2r, b3, nb_base + lmoff0);   // ksegs 0..3
                    ldsm_x4(b4, b5, b6,  b7, nb_base + lmoff1);    // ksegs 4..7
                    mma_f16(c[n], a[0], b0, b1r);
                    mma_f16(c[n], a[1], b2r, b3);
                    mma_f16(c[n], a[2], b4, b5);
                    mma_f16(c[n], a[3], b6, b7);
                }

                // region-aware contraction
                if (ch < 16) {                      // A (wa): u = 2ch + h2
#pragma unroll
                    for (int r = 0; r < 2; r++) {
                        const int er = r ? er1 : er0;
                        const float y = x0_s[er * 33 + 2 * ch + h2] * sh0_s[er];
#pragma unroll
                        for (int n = 0; n < 4; n++) {
                            acc0[r][n][0] = fmaf(c[n][r * 2 + 0], y, acc0[r][n][0]);
                            acc0[r][n][1] = fmaf(c[n][r * 2 + 1], y, acc0[r][n][1]);
                        }
                    }
                } else if (ch < 24) {               // C (wc): u = 4ch' + 2h2 + {0,1}
                    const int chp = ch - 16;
#pragma unroll
                    for (int r = 0; r < 2; r++) {
                        const int er = r ? er1 : er0;
                        const float xa = x0_s[er * 33 + 4 * chp + h2 * 2 + 0];
                        const float xb = x0_s[er * 33 + 4 * chp + h2 * 2 + 1];
#pragma unroll
                        for (int p = 0; p < 2; p++) {
                            cacc[r][p][0] = fmaf(c[p][r * 2 + 0], xa,
                                            fmaf(c[2 + p][r * 2 + 0], xb, cacc[r][p][0]));
                            cacc[r][p][1] = fmaf(c[p][r * 2 + 1], xa,
                                            fmaf(c[2 + p][r * 2 + 1], xb, cacc[r][p][1]));
                        }
                    }
                } else if (ch < 28) {               // D (wd): u = 4ch' + 2h2 + t
                    const int chp = ch - 24;
#pragma unroll
                    for (int r = 0; r < 2; r++) {
                        const int er = r ? er1 : er0;
#pragma unroll
                        for (int t = 0; t < 2; t++) {
                            const int u = 4 * chp + h2 * 2 + t;
                            const float za = z1_s[er * 49 + u * 3 + 0];
                            const float zb = z1_s[er * 49 + u * 3 + 1];
                            const float zc = z1_s[er * 49 + u * 3 + 2];
#pragma unroll
                            for (int p = 0; p < 2; p++) {
                                const int n = t * 2 + p;
#pragma unroll
                                for (int j = 0; j < 2; j++) {
                                    const float wv = c[n][r * 2 + j];
                                    dacc[r][p][j][0] = fmaf(wv, za, dacc[r][p][j][0]);
                                    dacc[r][p][j][1] = fmaf(wv, zb, dacc[r][p][j][1]);
                                    dacc[r][p][j][2] = fmaf(wv, zc, dacc[r][p][j][2]);
                                }
                            }
                        }
                    }
                } else {                            // B (wb): u = 2ch' + h2
                    const int chp = ch - 28;
#pragma unroll
                    for (int r = 0; r < 2; r++) {
                        const int er = r ? er1 : er0;
                        const float y = y1_s[er * 17 + 2 * chp + h2];
#pragma unroll
                        for (int n = 0; n < 4; n++) {
                            acc0[r][n][0] = fmaf(c[n][r * 2 + 0], y, acc0[r][n][0]);
                            acc0[r][n][1] = fmaf(c[n][r * 2 + 1], y, acc0[r][n][1]);
                        }
                    }
                }
            }
        }

        // ---- out0 writeout (cols 0..31, packed pairs) + count ----
#pragma unroll
        for (int r = 0; r < 2; r++) {
            const int er = r ? er1 : er0;
            if (eBase + er < E) {
                const int node = dst_s[er];
#pragma unroll
                for (int n = 0; n < 4; n++) {
                    const int col = n * 8 + 2 * qd;   // even -> 8B aligned
                    red_add2(&g_sums[node * 80 + col],
                             NORM_V * acc0[r][n][0], NORM_V * acc0[r][n][1]);
                }
                if (qd == 0) red_add1(&g_cnt[node], 1.0f);
            }
        }
    }
}

// ---------------------------------------------------------------------------
// residual + mean; restores g_sums/g_cnt/g_tile_ctr to zero (replay safe).
// 320 threads = 4 nodes/block; rw0/rw1 staged in smem; one rcp per node.
// ---------------------------------------------------------------------------
__global__ __launch_bounds__(320) void final_kernel(
    int n_nodes,
    const float* __restrict__ x_dst,
    const float* __restrict__ rw0,
    const float* __restrict__ rw1,
    float* __restrict__ out)
{
    __shared__ float w0s[1024];
    __shared__ float w1s[256];
    __shared__ float cs[4];
    const int tid = threadIdx.x;

    if (blockIdx.x == 0 && tid == 0) g_tile_ctr = 0u;   // reset work queue

    for (int i = tid; i < 1024; i += 320) w0s[i] = rw0[i];
    if (tid < 256) w1s[tid] = rw1[tid];

    const int local = tid / 80;
    const int j     = tid - local * 80;
    const int n     = blockIdx.x * 4 + local;
    const bool ok   = (n < n_nodes);

    if (ok && j == 0) cs[local] = 1.0f / fmaxf(g_cnt[n], 1.0f);
    __syncthreads();
    if (!ok) return;

    float res;
    if (j < 32) {
        float acc = 0.f;
#pragma unroll
        for (int u = 0; u < 32; u++)
            acc = fmaf(x_dst[n * 80 + u], w0s[u * 32 + j], acc);
        res = acc * RSQRT32_V;
    } else {
        const int w = (j - 32) / 3;
        const int m = (j - 32) - 3 * w;
        float acc = 0.f;
#pragma unroll
        for (int u = 0; u < 16; u++)
            acc = fmaf(x_dst[n * 80 + 32 + u * 3 + m], w1s[u * 16 + w], acc);
        res = acc * 0.25f;
    }
    const int idx = n * 80 + j;
    out[idx] = fmaf(g_sums[idx], cs[local], res);

    // restore zeros for next replay
    g_sums[idx] = 0.0f;
    if (j == 0) g_cnt[n] = 0.0f;
}

// ---------------------------------------------------------------------------
extern "C" void kernel_launch(void* const* d_in, const int* in_sizes, int n_in,
                              void* d_out, int out_size)
{
    const int*   dst       = (const int*)  d_in[0];
    const float* x_src     = (const float*)d_in[1];
    const float* x_dst     = (const float*)d_in[2];
    const float* sh        = (const float*)d_in[3];
    const float* edge_attr = (const float*)d_in[4];
    const float* w1        = (const float*)d_in[5];
    const float* b1        = (const float*)d_in[6];
    const float* w2        = (const float*)d_in[7];
    const float* b2        = (const float*)d_in[8];
    const float* rw0       = (const float*)d_in[9];
    const float* rw1       = (const float*)d_in[10];
    float* out = (float*)d_out;

    const int E       = in_sizes[0];
    const int n_nodes = in_sizes[2] / OUT_DIM;
    const int nTiles  = (E + 63) / 64;

    cudaFuncSetAttribute(edge_kernel,
                         cudaFuncAttributeMaxDynamicSharedMemorySize,
                         SMEM_BYTES);

    dim3 cblk(32, 8);
    convert_w2<<<72, cblk>>>(w2);
    edge_kernel<<<4 * 148, 128, SMEM_BYTES>>>(
        E, nTiles, dst, x_src, sh, edge_attr, w1, b1, b2);
    final_kernel<<<(n_nodes + 3) / 4, 320>>>(
        n_nodes, x_dst, rw0, rw1, out);
}

// round 16
// speedup vs baseline: 1.5533x; 1.5533x over previous
#include <cuda_runtime.h>
#include <cuda_fp16.h>

// ---------------------------------------------------------------------------
// Conv_2259152798130 — fused e3nn edge conv.
// R16 = R14/R12 exact revert (verified best: 142.0-142.5us, reproduced twice).
//   edge kernel: all-tensor-core MLPs (fp16 m16n8k16), cp.async 3-stage
//   pipeline, ldmatrix B fragments, packed red.global.add.v2 atomics,
//   out1 writeout hoisted under region-B mma, W1 staged fp32->fp16 in-kernel,
//   64-edge tiles / 128 threads / 4 CTAs/SM (static grid — the HW block
//   scheduler provides inter-tile overlap; R15's persistent-CTA variant
//   serialized tile prologues and regressed +80us).
//   convert_w2: 72-block smem-transpose (latency floor ~4.5us).
//   final_kernel: 4 nodes/block, weights in smem, per-node reciprocal.
// ---------------------------------------------------------------------------

#define NN       10000
#define OUT_DIM  80
#define NORM_V        0.14433756729740643f   // 1/sqrt(48)
#define INV_SQRT3_V   0.57735026918962576f
#define RSQRT32_V     0.17677669529663687f   // 1/sqrt(32)

// zero-initialized at module load; final_kernel restores zeros each run
__device__ float g_sums[NN * OUT_DIM];
__device__ float g_cnt[NN];
// W2 fp16: row j (out col) holds 64 k's as 32 half2 (128B rows)
__device__ unsigned g_w2h[2304 * 32];

// 72 blocks of (32,8): 32-col x 64-row W2 tiles via smem transpose.
// All global accesses 128B-coalesced.
__global__ void convert_w2(const float* __restrict__ w2) {
    __shared__ float s[64][33];
    const int x  = threadIdx.x;            // 0..31
    const int y  = threadIdx.y;            // 0..7
    const int j0 = blockIdx.x * 32;
#pragma unroll
    for (int r = 0; r < 8; r++) {          // coalesced 128B reads
        const int k = y * 8 + r;
        s[k][x] = w2[k * 2304 + j0 + x];
    }
    __syncthreads();
#pragma unroll
    for (int q = 0; q < 4; q++) {          // coalesced 128B writes (x = kp)
        const int jj = y * 4 + q;
        const __half2 h2 = __halves2half2(
            __float2half_rn(s[2 * x][jj]),
            __float2half_rn(s[2 * x + 1][jj]));
        g_w2h[(j0 + jj) * 32 + x] = *(const unsigned*)&h2;
    }
}

// mma m16n8k16 fp16 -> fp32 accum (A row-major, B col-major)
__device__ __forceinline__ void mma_f16(float c[4], const unsigned a[4],
                                        unsigned b0, unsigned b1) {
    asm volatile(
        "mma.sync.aligned.m16n8k16.row.col.f32.f16.f16.f32 "
        "{%0,%1,%2,%3}, {%4,%5,%6,%7}, {%8,%9}, {%0,%1,%2,%3};"
        : "+f"(c[0]), "+f"(c[1]), "+f"(c[2]), "+f"(c[3])
        : "r"(a[0]), "r"(a[1]), "r"(a[2]), "r"(a[3]), "r"(b0), "r"(b1));
}

__device__ __forceinline__ void ldsm_x4(unsigned& r0, unsigned& r1,
                                        unsigned& r2, unsigned& r3,
                                        unsigned addr) {
    asm volatile("ldmatrix.sync.aligned.m8n8.x4.shared.b16 {%0,%1,%2,%3}, [%4];"
                 : "=r"(r0), "=r"(r1), "=r"(r2), "=r"(r3) : "r"(addr));
}

// packed / scalar global reductions (no return)
__device__ __forceinline__ void red_add2(float* a, float x, float y) {
    asm volatile("red.global.add.v2.f32 [%0], {%1, %2};"
                 :: "l"(a), "f"(x), "f"(y) : "memory");
}
__device__ __forceinline__ void red_add1(float* a, float x) {
    asm volatile("red.global.add.f32 [%0], %1;"
                 :: "l"(a), "f"(x) : "memory");
}

__device__ __forceinline__ void cp_commit() {
    asm volatile("cp.async.commit_group;" ::: "memory");
}
template <int N>
__device__ __forceinline__ void cp_wait() {
    asm volatile("cp.async.wait_group %0;" :: "n"(N) : "memory");
}

// prefetch one W2 chunk: 64 rows x 128B, seg ^= (n&7) swizzle, + 64 b2 floats
// 512 x 16B segments over 128 threads (4 each)
__device__ __forceinline__ void prefetch_chunk(
    unsigned wbuf_b, float* bbuf, const float* __restrict__ b2,
    int ch, int tid)
{
#pragma unroll
    for (int t = 0; t < 4; t++) {
        const int i = tid + t * 128;       // 0..511
        const int n = i >> 3;              // row (out col) 0..63
        const int s = i & 7;               // 16B segment within row
        const unsigned dst = wbuf_b + (unsigned)(n * 128 + ((s ^ (n & 7)) << 4));
        const char* src = (const char*)g_w2h + (size_t)(ch * 64 + n) * 128 + s * 16;
        asm volatile("cp.async.cg.shared.global [%0], [%1], 16;"
                     :: "r"(dst), "l"(src));
    }
    if (tid < 16) {
        unsigned dst;
        asm("{ .reg .u64 t; cvta.to.shared.u64 t, %1; cvt.u32.u64 %0, t; }"
            : "=r"(dst) : "l"(bbuf + tid * 4));
        const float* src = b2 + ch * 64 + tid * 4;
        asm volatile("cp.async.cg.shared.global [%0], [%1], 16;"
                     :: "r"(dst), "l"(src));
    }
}

// ---------------------------------------------------------------------------
// Shared layout (4-byte units), 64 edges/block, total 14144 = 56576 B
//   attrh [64][17] u32 @ 0      (attr fp16 pairs)
//   b1s   [64]         @ 1088
//   Wst   [3][2048]u32 @ 1152   (fp16 stages; buf0 = W1 during MLP1)
//   b2st  [3][64]      @ 7296
//   x0_s  [64][33]     @ 7488
//   y1_s  [64][17]     @ 9600
//   z1_s  [64][49]     @ 10688
//   sh0_s [64]         @ 13824
//   sh1_s [64][3]      @ 13888
//   dst_s [64] int     @ 14080
// ---------------------------------------------------------------------------
#define SMEM_BYTES (14144 * 4)

__global__ __launch_bounds__(128, 4) void edge_kernel(
    int E,
    const int*   __restrict__ dst,
    const float* __restrict__ x_src,
    const float* __restrict__ sh,
    const float* __restrict__ edge_attr,
    const float* __restrict__ w1,
    const float* __restrict__ b1,
    const float* __restrict__ b2)
{
    extern __shared__ float smem[];
    unsigned* attrh = (unsigned*)smem;
    float* b1s   = smem + 1088;
    float* b2st  = smem + 7296;
    float* x0_s  = smem + 7488;
    float* y1_s  = smem + 9600;
    float* z1_s  = smem + 10688;
    float* sh0_s = smem + 13824;
    float* sh1_s = smem + 13888;
    int*   dst_s = (int*)(smem + 14080);

    unsigned wst_b;                        // byte smem addr of Wst
    asm("{ .reg .u64 t; cvta.to.shared.u64 t, %1; cvt.u32.u64 %0, t; }"
        : "=r"(wst_b) : "l"(smem + 1152));

    const int tid   = threadIdx.x;
    const int eBase = blockIdx.x * 64;
    const int e     = tid & 63;
    const int half  = tid >> 6;
    const int ge    = eBase + e;
    const bool valid = (ge < E);

    // ---- kick off cp.async: chunk0 -> buf1, chunk1 -> buf2 (2 groups) ----
    prefetch_chunk(wst_b + 8192,  b2st + 64,  b2, 0, tid);      cp_commit();
    prefetch_chunk(wst_b + 16384, b2st + 128, b2, 1, tid);      cp_commit();

    // ---- stage W1 fp32 -> fp16 into Wst buf0 (ldmatrix layout, ksegs 0..3;
    //      ksegs 4..7 are never read by MLP1's lmoff0, no zero fill needed).
    //      Reads are 128B-coalesced (lanes span n); hidden under phase 0. ----
    {
        const int nW = (tid & 31) | (((tid >> 5) & 1) << 5);  // n: 0..63
        const int pb = (tid >> 6) << 3;                       // p base: 0 or 8
#pragma unroll
        for (int pp = 0; pp < 8; pp++) {
            const int p  = pb + pp;                           // half2 idx 0..15
            const float v0 = w1[(2 * p)     * 64 + nW];
            const float v1 = w1[(2 * p + 1) * 64 + nW];
            const __half2 h2 = __halves2half2(__float2half_rn(v0),
                                              __float2half_rn(v1));
            const unsigned addr = wst_b +
                (unsigned)(nW * 128 + (((p >> 2) ^ (nW & 7)) << 4) + (p & 3) * 4);
            asm volatile("st.shared.b32 [%0], %1;"
                         :: "r"(addr), "r"(*(const unsigned*)&h2));
        }
    }

    // ---- Phase 0: per-edge features + attr fp16 ----
    if (tid < 64) b1s[tid] = b1[tid];

    {   // attr: thread (e, half) converts 16 of 32 attrs
        const float* ap = edge_attr + (size_t)ge * 32 + half * 16;
#pragma unroll
        for (int q = 0; q < 4; q++) {
            float4 v = valid ? ((const float4*)ap)[q]
                             : make_float4(0.f, 0.f, 0.f, 0.f);
            __half2 p0 = __halves2half2(__float2half_rn(v.x), __float2half_rn(v.y));
            __half2 p1 = __halves2half2(__float2half_rn(v.z), __float2half_rn(v.w));
            attrh[e * 17 + half * 8 + q * 2]     = *(const unsigned*)&p0;
            attrh[e * 17 + half * 8 + q * 2 + 1] = *(const unsigned*)&p1;
        }
    }

    if (half == 0) {   // one thread per edge
        dst_s[e] = valid ? dst[ge] : 0;
        float s0 = 0.f, s1 = 0.f, s2 = 0.f, s3 = 0.f;
        if (valid) {
            const float4 shv = *(const float4*)&sh[ge * 4];
            s0 = shv.x; s1 = shv.y; s2 = shv.z; s3 = shv.w;
        }
        sh0_s[e] = s0;
        sh1_s[e * 3 + 0] = s1; sh1_s[e * 3 + 1] = s2; sh1_s[e * 3 + 2] = s3;
#pragma unroll
        for (int q = 0; q < 8; q++) {
            float4 v = valid ? ((const float4*)&x_src[ge * 80])[q]
                             : make_float4(0.f, 0.f, 0.f, 0.f);
            x0_s[e * 33 + q * 4 + 0] = v.x;
            x0_s[e * 33 + q * 4 + 1] = v.y;
            x0_s[e * 33 + q * 4 + 2] = v.z;
            x0_s[e * 33 + q * 4 + 3] = v.w;
        }
#pragma unroll
        for (int u = 0; u < 16; u++) {
            float a = 0.f, b = 0.f, c = 0.f;
            if (valid) {
                a = x_src[ge * 80 + 32 + u * 3 + 0];
                b = x_src[ge * 80 + 32 + u * 3 + 1];
                c = x_src[ge * 80 + 32 + u * 3 + 2];
            }
            y1_s[e * 17 + u] = INV_SQRT3_V * (a * s1 + b * s2 + c * s3);
            z1_s[e * 49 + u * 3 + 0] = a * s0;
            z1_s[e * 49 + u * 3 + 1] = b * s0;
            z1_s[e * 49 + u * 3 + 2] = c * s0;
        }
    }

    __syncthreads();   // W1 STS + attrh + features visible

    // ---- warp identity ----
    const int lane = tid & 31;
    const int warp = tid >> 5;          // 0..3 -> edges warp*16 .. +15
    const int gid  = lane >> 2;
    const int qd   = lane & 3;
    const int er0  = warp * 16 + gid;
    const int er1  = er0 + 8;

    const int lrow = lane & 7;
    const int lmat = lane >> 3;
    const unsigned lmoff0 = (unsigned)(lrow * 128 + (((lmat)     ^ lrow) << 4));
    const unsigned lmoff1 = (unsigned)(lrow * 128 + (((lmat | 4) ^ lrow) << 4));

    // ---- MLP1 via mma: h fragments land directly in main-GEMM A regs ----
    unsigned a[4][4];
    {
        unsigned am[2][4];
        am[0][0] = attrh[er0 * 17 + qd];
        am[0][1] = attrh[er1 * 17 + qd];
        am[0][2] = attrh[er0 * 17 + 4 + qd];
        am[0][3] = attrh[er1 * 17 + 4 + qd];
        am[1][0] = attrh[er0 * 17 + 8 + qd];
        am[1][1] = attrh[er1 * 17 + 8 + qd];
        am[1][2] = attrh[er0 * 17 + 12 + qd];
        am[1][3] = attrh[er1 * 17 + 12 + qd];

#pragma unroll
        for (int t = 0; t < 8; t++) {
            float c[4];
            const float bb0 = b1s[t * 8 + 2 * qd];
            const float bb1 = b1s[t * 8 + 2 * qd + 1];
            c[0] = bb0; c[1] = bb1; c[2] = bb0; c[3] = bb1;
            unsigned b0, b1r, b2r, b3;
            ldsm_x4(b0, b1r, b2r, b3, wst_b + (unsigned)(t * 1024) + lmoff0);
            mma_f16(c, am[0], b0, b1r);
            mma_f16(c, am[1], b2r, b3);
            const __half2 plo = __halves2half2(
                __float2half_rn(fmaxf(c[0], 0.f)), __float2half_rn(fmaxf(c[1], 0.f)));
            const __half2 phi = __halves2half2(
                __float2half_rn(fmaxf(c[2], 0.f)), __float2half_rn(fmaxf(c[3], 0.f)));
            a[t >> 1][(t & 1) * 2 + 0] = *(const unsigned*)&plo;
            a[t >> 1][(t & 1) * 2 + 1] = *(const unsigned*)&phi;
        }
    }

    // accumulators
    float acc0[2][4][2];
    float cacc[2][2][2];
    float dacc[2][2][2][3];
#pragma unroll
    for (int r = 0; r < 2; r++) {
#pragma unroll
        for (int n = 0; n < 4; n++) { acc0[r][n][0] = 0.f; acc0[r][n][1] = 0.f; }
#pragma unroll
        for (int p = 0; p < 2; p++) {
            cacc[r][p][0] = 0.f; cacc[r][p][1] = 0.f;
#pragma unroll
            for (int j = 0; j < 2; j++) {
                dacc[r][p][j][0] = 0.f; dacc[r][p][j][1] = 0.f; dacc[r][p][j][2] = 0.f;
            }
        }
    }

    // ---- main pipelined loop: chunk ch lives in buf (ch+1)%3 ----
#pragma unroll 1
    for (int ch = 0; ch < 36; ch++) {
        cp_wait<1>();          // chunk ch resident (own thread's view)
        __syncthreads();       // visible to all; buf ch%3 free (W1 dead at ch=0)
        if (ch + 2 < 36)
            prefetch_chunk(wst_b + (unsigned)((ch % 3) * 8192),
                           b2st + (ch % 3) * 64,
                           b2, ch + 2, tid);
        cp_commit();           // always commit to keep group cadence

        // ---- hoisted out1 writeout: cacc/dacc final after region D (ch 27);
        //      overlaps the remaining 8 region-B chunks of mma work ----
        if (ch == 28) {
#pragma unroll
            for (int r = 0; r < 2; r++) {
                const int er = r ? er1 : er0;
                if (eBase + er < E) {
                    const int node = dst_s[er];
                    const float s1v = sh1_s[er * 3 + 0];
                    const float s2v = sh1_s[er * 3 + 1];
                    const float s3v = sh1_s[er * 3 + 2];
#pragma unroll
                    for (int p = 0; p < 2; p++) {
                        const int v0 = p * 8 + 2 * qd;          // j = 0 (even v)
                        float* base0 = &g_sums[node * 80 + 32 + v0 * 3];
                        {
                            const float cc = cacc[r][p][0];
                            red_add2(base0,
                                     NORM_V * (s1v * cc + dacc[r][p][0][0]),
                                     NORM_V * (s2v * cc + dacc[r][p][0][1]));
                            red_add1(base0 + 2,
                                     NORM_V * (s3v * cc + dacc[r][p][0][2]));
                        }
                        {                                        // j = 1 (odd v)
                            const float cc = cacc[r][p][1];
                            red_add1(base0 + 3,
                                     NORM_V * (s1v * cc + dacc[r][p][1][0]));
                            red_add2(base0 + 4,
                                     NORM_V * (s2v * cc + dacc[r][p][1][1]),
                                     NORM_V * (s3v * cc + dacc[r][p][1][2]));
                        }
                    }
                }
            }
        }

        const unsigned chunk_b = wst_b + (unsigned)(((ch + 1) % 3) * 8192);
        const float*   bb      = b2st + ((ch + 1) % 3) * 64;

#pragma unroll
        for (int h2 = 0; h2 < 2; h2++) {
            float c[4][4];
#pragma unroll
            for (int n = 0; n < 4; n++) {
                const float bb0 = bb[(h2 * 4 + n) * 8 + 2 * qd];
                const float bb1 = bb[(h2 * 4 + n) * 8 + 2 * qd + 1];
                c[n][0] = bb0; c[n][1] = bb1; c[n][2] = bb0; c[n][3] = bb1;
            }
#pragma unroll
            for (int n = 0; n < 4; n++) {
                const unsigned nb_base = chunk_b + (unsigned)((h2 * 4 + n) * 1024);
                unsigned b0, b1r, b2r, b3, b4, b5, b6, b7;
                ldsm_x4(b0, b1r, b2r, b3, nb_base + lmoff0);   // ksegs 0..3
                ldsm_x4(b4, b5, b6,  b7, nb_base + lmoff1);    // ksegs 4..7
                mma_f16(c[n], a[0], b0, b1r);
                mma_f16(c[n], a[1], b2r, b3);
                mma_f16(c[n], a[2], b4, b5);
                mma_f16(c[n], a[3], b6, b7);
            }

            // region-aware contraction
            if (ch < 16) {                      // A (wa): u = 2ch + h2
#pragma unroll
                for (int r = 0; r < 2; r++) {
                    const int er = r ? er1 : er0;
                    const float y = x0_s[er * 33 + 2 * ch + h2] * sh0_s[er];
#pragma unroll
                    for (int n = 0; n < 4; n++) {
                        acc0[r][n][0] = fmaf(c[n][r * 2 + 0], y, acc0[r][n][0]);
                        acc0[r][n][1] = fmaf(c[n][r * 2 + 1], y, acc0[r][n][1]);
                    }
                }
            } else if (ch < 24) {               // C (wc): u = 4ch' + 2h2 + {0,1}
                const int chp = ch - 16;
#pragma unroll
                for (int r = 0; r < 2; r++) {
                    const int er = r ? er1 : er0;
                    const float xa = x0_s[er * 33 + 4 * chp + h2 * 2 + 0];
                    const float xb = x0_s[er * 33 + 4 * chp + h2 * 2 + 1];
#pragma unroll
                    for (int p = 0; p < 2; p++) {
                        cacc[r][p][0] = fmaf(c[p][r * 2 + 0], xa,
                                        fmaf(c[2 + p][r * 2 + 0], xb, cacc[r][p][0]));
                        cacc[r][p][1] = fmaf(c[p][r * 2 + 1], xa,
                                        fmaf(c[2 + p][r * 2 + 1], xb, cacc[r][p][1]));
                    }
                }
            } else if (ch < 28) {               // D (wd): u = 4ch' + 2h2 + t
                const int chp = ch - 24;
#pragma unroll
                for (int r = 0; r < 2; r++) {
                    const int er = r ? er1 : er0;
#pragma unroll
                    for (int t = 0; t < 2; t++) {
                        const int u = 4 * chp + h2 * 2 + t;
                        const float za = z1_s[er * 49 + u * 3 + 0];
                        const float zb = z1_s[er * 49 + u * 3 + 1];
                        const float zc = z1_s[er * 49 + u * 3 + 2];
#pragma unroll
                        for (int p = 0; p < 2; p++) {
                            const int n = t * 2 + p;
#pragma unroll
                            for (int j = 0; j < 2; j++) {
                                const float wv = c[n][r * 2 + j];
                                dacc[r][p][j][0] = fmaf(wv, za, dacc[r][p][j][0]);
                                dacc[r][p][j][1] = fmaf(wv, zb, dacc[r][p][j][1]);
                                dacc[r][p][j][2] = fmaf(wv, zc, dacc[r][p][j][2]);
                            }
                        }
                    }
                }
            } else {                            // B (wb): u = 2ch' + h2
                const int chp = ch - 28;
#pragma unroll
                for (int r = 0; r < 2; r++) {
                    const int er = r ? er1 : er0;
                    const float y = y1_s[er * 17 + 2 * chp + h2];
#pragma unroll
                    for (int n = 0; n < 4; n++) {
                        acc0[r][n][0] = fmaf(c[n][r * 2 + 0], y, acc0[r][n][0]);
                        acc0[r][n][1] = fmaf(c[n][r * 2 + 1], y, acc0[r][n][1]);
                    }
                }
            }
        }
    }

    // ---- out0 writeout (cols 0..31, packed pairs) + count ----
#pragma unroll
    for (int r = 0; r < 2; r++) {
        const int er = r ? er1 : er0;
        if (eBase + er < E) {
            const int node = dst_s[er];
#pragma unroll
            for (int n = 0; n < 4; n++) {
                const int col = n * 8 + 2 * qd;       // even -> 8B aligned
                red_add2(&g_sums[node * 80 + col],
                         NORM_V * acc0[r][n][0], NORM_V * acc0[r][n][1]);
            }
            if (qd == 0) red_add1(&g_cnt[node], 1.0f);
        }
    }
}

// ---------------------------------------------------------------------------
// residual + mean; restores g_sums/g_cnt to zero (graph-replay safe).
// 320 threads = 4 nodes/block; rw0/rw1 staged in smem; one rcp per node.
// ---------------------------------------------------------------------------
__global__ __launch_bounds__(320) void final_kernel(
    int n_nodes,
    const float* __restrict__ x_dst,
    const float* __restrict__ rw0,
    const float* __restrict__ rw1,
    float* __restrict__ out)
{
    __shared__ float w0s[1024];
    __shared__ float w1s[256];
    __shared__ float cs[4];
    const int tid = threadIdx.x;

    for (int i = tid; i < 1024; i += 320) w0s[i] = rw0[i];
    if (tid < 256) w1s[tid] = rw1[tid];

    const int local = tid / 80;
    const int j     = tid - local * 80;
    const int n     = blockIdx.x * 4 + local;
    const bool ok   = (n < n_nodes);

    if (ok && j == 0) cs[local] = 1.0f / fmaxf(g_cnt[n], 1.0f);
    __syncthreads();
    if (!ok) return;

    float res;
    if (j < 32) {
        float acc = 0.f;
#pragma unroll
        for (int u = 0; u < 32; u++)
            acc = fmaf(x_dst[n * 80 + u], w0s[u * 32 + j], acc);
        res = acc * RSQRT32_V;
    } else {
        const int w = (j - 32) / 3;
        const int m = (j - 32) - 3 * w;
        float acc = 0.f;
#pragma unroll
        for (int u = 0; u < 16; u++)
            acc = fmaf(x_dst[n * 80 + 32 + u * 3 + m], w1s[u * 16 + w], acc);
        res = acc * 0.25f;
    }
    const int idx = n * 80 + j;
    out[idx] = fmaf(g_sums[idx], cs[local], res);

    // restore zeros for next replay
    g_sums[idx] = 0.0f;
    if (j == 0) g_cnt[n] = 0.0f;
}

// ---------------------------------------------------------------------------
extern "C" void kernel_launch(void* const* d_in, const int* in_sizes, int n_in,
                              void* d_out, int out_size)
{
    const int*   dst       = (const int*)  d_in[0];
    const float* x_src     = (const float*)d_in[1];
    const float* x_dst     = (const float*)d_in[2];
    const float* sh        = (const float*)d_in[3];
    const float* edge_attr = (const float*)d_in[4];
    const float* w1        = (const float*)d_in[5];
    const float* b1        = (const float*)d_in[6];
    const float* w2        = (const float*)d_in[7];
    const float* b2        = (const float*)d_in[8];
    const float* rw0       = (const float*)d_in[9];
    const float* rw1       = (const float*)d_in[10];
    float* out = (float*)d_out;

    const int E       = in_sizes[0];
    const int n_nodes = in_sizes[2] / OUT_DIM;

    cudaFuncSetAttribute(edge_kernel,
                         cudaFuncAttributeMaxDynamicSharedMemorySize,
                         SMEM_BYTES);

    dim3 cblk(32, 8);
    convert_w2<<<72, cblk>>>(w2);
    edge_kernel<<<(E + 63) / 64, 128, SMEM_BYTES>>>(
        E, dst, x_src, sh, edge_attr, w1, b1, b2);
    final_kernel<<<(n_nodes + 3) / 4, 320>>>(
        n_nodes, x_dst, rw0, rw1, out);
}

// round 17
// speedup vs baseline: 1.5878x; 1.0222x over previous
#include <cuda_runtime.h>
#include <cuda_fp16.h>

// ---------------------------------------------------------------------------
// Conv_2259152798130 — fused e3nn edge conv.
// R17 = R16 (verified best 142.0-142.8us, triple-reproduced) + out1 writeout
// packed as 3x red.global.add.v2 (was red2,red1,red1,red2): v0 is always even
// so the whole 6-float group is 8B-aligned. Strict instruction reduction,
// everything else byte-identical.
// ---------------------------------------------------------------------------

#define NN       10000
#define OUT_DIM  80
#define NORM_V        0.14433756729740643f   // 1/sqrt(48)
#define INV_SQRT3_V   0.57735026918962576f
#define RSQRT32_V     0.17677669529663687f   // 1/sqrt(32)

// zero-initialized at module load; final_kernel restores zeros each run
__device__ float g_sums[NN * OUT_DIM];
__device__ float g_cnt[NN];
// W2 fp16: row j (out col) holds 64 k's as 32 half2 (128B rows)
__device__ unsigned g_w2h[2304 * 32];

// 72 blocks of (32,8): 32-col x 64-row W2 tiles via smem transpose.
// All global accesses 128B-coalesced.
__global__ void convert_w2(const float* __restrict__ w2) {
    __shared__ float s[64][33];
    const int x  = threadIdx.x;            // 0..31
    const int y  = threadIdx.y;            // 0..7
    const int j0 = blockIdx.x * 32;
#pragma unroll
    for (int r = 0; r < 8; r++) {          // coalesced 128B reads
        const int k = y * 8 + r;
        s[k][x] = w2[k * 2304 + j0 + x];
    }
    __syncthreads();
#pragma unroll
    for (int q = 0; q < 4; q++) {          // coalesced 128B writes (x = kp)
        const int jj = y * 4 + q;
        const __half2 h2 = __halves2half2(
            __float2half_rn(s[2 * x][jj]),
            __float2half_rn(s[2 * x + 1][jj]));
        g_w2h[(j0 + jj) * 32 + x] = *(const unsigned*)&h2;
    }
}

// mma m16n8k16 fp16 -> fp32 accum (A row-major, B col-major)
__device__ __forceinline__ void mma_f16(float c[4], const unsigned a[4],
                                        unsigned b0, unsigned b1) {
    asm volatile(
        "mma.sync.aligned.m16n8k16.row.col.f32.f16.f16.f32 "
        "{%0,%1,%2,%3}, {%4,%5,%6,%7}, {%8,%9}, {%0,%1,%2,%3};"
        : "+f"(c[0]), "+f"(c[1]), "+f"(c[2]), "+f"(c[3])
        : "r"(a[0]), "r"(a[1]), "r"(a[2]), "r"(a[3]), "r"(b0), "r"(b1));
}

__device__ __forceinline__ void ldsm_x4(unsigned& r0, unsigned& r1,
                                        unsigned& r2, unsigned& r3,
                                        unsigned addr) {
    asm volatile("ldmatrix.sync.aligned.m8n8.x4.shared.b16 {%0,%1,%2,%3}, [%4];"
                 : "=r"(r0), "=r"(r1), "=r"(r2), "=r"(r3) : "r"(addr));
}

// packed / scalar global reductions (no return)
__device__ __forceinline__ void red_add2(float* a, float x, float y) {
    asm volatile("red.global.add.v2.f32 [%0], {%1, %2};"
                 :: "l"(a), "f"(x), "f"(y) : "memory");
}
__device__ __forceinline__ void red_add1(float* a, float x) {
    asm volatile("red.global.add.f32 [%0], %1;"
                 :: "l"(a), "f"(x) : "memory");
}

__device__ __forceinline__ void cp_commit() {
    asm volatile("cp.async.commit_group;" ::: "memory");
}
template <int N>
__device__ __forceinline__ void cp_wait() {
    asm volatile("cp.async.wait_group %0;" :: "n"(N) : "memory");
}

// prefetch one W2 chunk: 64 rows x 128B, seg ^= (n&7) swizzle, + 64 b2 floats
// 512 x 16B segments over 128 threads (4 each)
__device__ __forceinline__ void prefetch_chunk(
    unsigned wbuf_b, float* bbuf, const float* __restrict__ b2,
    int ch, int tid)
{
#pragma unroll
    for (int t = 0; t < 4; t++) {
        const int i = tid + t * 128;       // 0..511
        const int n = i >> 3;              // row (out col) 0..63
        const int s = i & 7;               // 16B segment within row
        const unsigned dst = wbuf_b + (unsigned)(n * 128 + ((s ^ (n & 7)) << 4));
        const char* src = (const char*)g_w2h + (size_t)(ch * 64 + n) * 128 + s * 16;
        asm volatile("cp.async.cg.shared.global [%0], [%1], 16;"
                     :: "r"(dst), "l"(src));
    }
    if (tid < 16) {
        unsigned dst;
        asm("{ .reg .u64 t; cvta.to.shared.u64 t, %1; cvt.u32.u64 %0, t; }"
            : "=r"(dst) : "l"(bbuf + tid * 4));
        const float* src = b2 + ch * 64 + tid * 4;
        asm volatile("cp.async.cg.shared.global [%0], [%1], 16;"
                     :: "r"(dst), "l"(src));
    }
}

// ---------------------------------------------------------------------------
// Shared layout (4-byte units), 64 edges/block, total 14144 = 56576 B
//   attrh [64][17] u32 @ 0      (attr fp16 pairs)
//   b1s   [64]         @ 1088
//   Wst   [3][2048]u32 @ 1152   (fp16 stages; buf0 = W1 during MLP1)
//   b2st  [3][64]      @ 7296
//   x0_s  [64][33]     @ 7488
//   y1_s  [64][17]     @ 9600
//   z1_s  [64][49]     @ 10688
//   sh0_s [64]         @ 13824
//   sh1_s [64][3]      @ 13888
//   dst_s [64] int     @ 14080
// ---------------------------------------------------------------------------
#define SMEM_BYTES (14144 * 4)

__global__ __launch_bounds__(128, 4) void edge_kernel(
    int E,
    const int*   __restrict__ dst,
    const float* __restrict__ x_src,
    const float* __restrict__ sh,
    const float* __restrict__ edge_attr,
    const float* __restrict__ w1,
    const float* __restrict__ b1,
    const float* __restrict__ b2)
{
    extern __shared__ float smem[];
    unsigned* attrh = (unsigned*)smem;
    float* b1s   = smem + 1088;
    float* b2st  = smem + 7296;
    float* x0_s  = smem + 7488;
    float* y1_s  = smem + 9600;
    float* z1_s  = smem + 10688;
    float* sh0_s = smem + 13824;
    float* sh1_s = smem + 13888;
    int*   dst_s = (int*)(smem + 14080);

    unsigned wst_b;                        // byte smem addr of Wst
    asm("{ .reg .u64 t; cvta.to.shared.u64 t, %1; cvt.u32.u64 %0, t; }"
        : "=r"(wst_b) : "l"(smem + 1152));

    const int tid   = threadIdx.x;
    const int eBase = blockIdx.x * 64;
    const int e     = tid & 63;
    const int half  = tid >> 6;
    const int ge    = eBase + e;
    const bool valid = (ge < E);

    // ---- kick off cp.async: chunk0 -> buf1, chunk1 -> buf2 (2 groups) ----
    prefetch_chunk(wst_b + 8192,  b2st + 64,  b2, 0, tid);      cp_commit();
    prefetch_chunk(wst_b + 16384, b2st + 128, b2, 1, tid);      cp_commit();

    // ---- stage W1 fp32 -> fp16 into Wst buf0 (ldmatrix layout, ksegs 0..3;
    //      ksegs 4..7 are never read by MLP1's lmoff0, no zero fill needed).
    //      Reads are 128B-coalesced (lanes span n); hidden under phase 0. ----
    {
        const int nW = (tid & 31) | (((tid >> 5) & 1) << 5);  // n: 0..63
        const int pb = (tid >> 6) << 3;                       // p base: 0 or 8
#pragma unroll
        for (int pp = 0; pp < 8; pp++) {
            const int p  = pb + pp;                           // half2 idx 0..15
            const float v0 = w1[(2 * p)     * 64 + nW];
            const float v1 = w1[(2 * p + 1) * 64 + nW];
            const __half2 h2 = __halves2half2(__float2half_rn(v0),
                                              __float2half_rn(v1));
            const unsigned addr = wst_b +
                (unsigned)(nW * 128 + (((p >> 2) ^ (nW & 7)) << 4) + (p & 3) * 4);
            asm volatile("st.shared.b32 [%0], %1;"
                         :: "r"(addr), "r"(*(const unsigned*)&h2));
        }
    }

    // ---- Phase 0: per-edge features + attr fp16 ----
    if (tid < 64) b1s[tid] = b1[tid];

    {   // attr: thread (e, half) converts 16 of 32 attrs
        const float* ap = edge_attr + (size_t)ge * 32 + half * 16;
#pragma unroll
        for (int q = 0; q < 4; q++) {
            float4 v = valid ? ((const float4*)ap)[q]
                             : make_float4(0.f, 0.f, 0.f, 0.f);
            __half2 p0 = __halves2half2(__float2half_rn(v.x), __float2half_rn(v.y));
            __half2 p1 = __halves2half2(__float2half_rn(v.z), __float2half_rn(v.w));
            attrh[e * 17 + half * 8 + q * 2]     = *(const unsigned*)&p0;
            attrh[e * 17 + half * 8 + q * 2 + 1] = *(const unsigned*)&p1;
        }
    }

    if (half == 0) {   // one thread per edge
        dst_s[e] = valid ? dst[ge] : 0;
        float s0 = 0.f, s1 = 0.f, s2 = 0.f, s3 = 0.f;
        if (valid) {
            const float4 shv = *(const float4*)&sh[ge * 4];
            s0 = shv.x; s1 = shv.y; s2 = shv.z; s3 = shv.w;
        }
        sh0_s[e] = s0;
        sh1_s[e * 3 + 0] = s1; sh1_s[e * 3 + 1] = s2; sh1_s[e * 3 + 2] = s3;
#pragma unroll
        for (int q = 0; q < 8; q++) {
            float4 v = valid ? ((const float4*)&x_src[ge * 80])[q]
                             : make_float4(0.f, 0.f, 0.f, 0.f);
            x0_s[e * 33 + q * 4 + 0] = v.x;
            x0_s[e * 33 + q * 4 + 1] = v.y;
            x0_s[e * 33 + q * 4 + 2] = v.z;
            x0_s[e * 33 + q * 4 + 3] = v.w;
        }
#pragma unroll
        for (int u = 0; u < 16; u++) {
            float a = 0.f, b = 0.f, c = 0.f;
            if (valid) {
                a = x_src[ge * 80 + 32 + u * 3 + 0];
                b = x_src[ge * 80 + 32 + u * 3 + 1];
                c = x_src[ge * 80 + 32 + u * 3 + 2];
            }
            y1_s[e * 17 + u] = INV_SQRT3_V * (a * s1 + b * s2 + c * s3);
            z1_s[e * 49 + u * 3 + 0] = a * s0;
            z1_s[e * 49 + u * 3 + 1] = b * s0;
            z1_s[e * 49 + u * 3 + 2] = c * s0;
        }
    }

    __syncthreads();   // W1 STS + attrh + features visible

    // ---- warp identity ----
    const int lane = tid & 31;
    const int warp = tid >> 5;          // 0..3 -> edges warp*16 .. +15
    const int gid  = lane >> 2;
    const int qd   = lane & 3;
    const int er0  = warp * 16 + gid;
    const int er1  = er0 + 8;

    const int lrow = lane & 7;
    const int lmat = lane >> 3;
    const unsigned lmoff0 = (unsigned)(lrow * 128 + (((lmat)     ^ lrow) << 4));
    const unsigned lmoff1 = (unsigned)(lrow * 128 + (((lmat | 4) ^ lrow) << 4));

    // ---- MLP1 via mma: h fragments land directly in main-GEMM A regs ----
    unsigned a[4][4];
    {
        unsigned am[2][4];
        am[0][0] = attrh[er0 * 17 + qd];
        am[0][1] = attrh[er1 * 17 + qd];
        am[0][2] = attrh[er0 * 17 + 4 + qd];
        am[0][3] = attrh[er1 * 17 + 4 + qd];
        am[1][0] = attrh[er0 * 17 + 8 + qd];
        am[1][1] = attrh[er1 * 17 + 8 + qd];
        am[1][2] = attrh[er0 * 17 + 12 + qd];
        am[1][3] = attrh[er1 * 17 + 12 + qd];

#pragma unroll
        for (int t = 0; t < 8; t++) {
            float c[4];
            const float bb0 = b1s[t * 8 + 2 * qd];
            const float bb1 = b1s[t * 8 + 2 * qd + 1];
            c[0] = bb0; c[1] = bb1; c[2] = bb0; c[3] = bb1;
            unsigned b0, b1r, b2r, b3;
            ldsm_x4(b0, b1r, b2r, b3, wst_b + (unsigned)(t * 1024) + lmoff0);
            mma_f16(c, am[0], b0, b1r);
            mma_f16(c, am[1], b2r, b3);
            const __half2 plo = __halves2half2(
                __float2half_rn(fmaxf(c[0], 0.f)), __float2half_rn(fmaxf(c[1], 0.f)));
            const __half2 phi = __halves2half2(
                __float2half_rn(fmaxf(c[2], 0.f)), __float2half_rn(fmaxf(c[3], 0.f)));
            a[t >> 1][(t & 1) * 2 + 0] = *(const unsigned*)&plo;
            a[t >> 1][(t & 1) * 2 + 1] = *(const unsigned*)&phi;
        }
    }

    // accumulators
    float acc0[2][4][2];
    float cacc[2][2][2];
    float dacc[2][2][2][3];
#pragma unroll
    for (int r = 0; r < 2; r++) {
#pragma unroll
        for (int n = 0; n < 4; n++) { acc0[r][n][0] = 0.f; acc0[r][n][1] = 0.f; }
#pragma unroll
        for (int p = 0; p < 2; p++) {
            cacc[r][p][0] = 0.f; cacc[r][p][1] = 0.f;
#pragma unroll
            for (int j = 0; j < 2; j++) {
                dacc[r][p][j][0] = 0.f; dacc[r][p][j][1] = 0.f; dacc[r][p][j][2] = 0.f;
            }
        }
    }

    // ---- main pipelined loop: chunk ch lives in buf (ch+1)%3 ----
#pragma unroll 1
    for (int ch = 0; ch < 36; ch++) {
        cp_wait<1>();          // chunk ch resident (own thread's view)
        __syncthreads();       // visible to all; buf ch%3 free (W1 dead at ch=0)
        if (ch + 2 < 36)
            prefetch_chunk(wst_b + (unsigned)((ch % 3) * 8192),
                           b2st + (ch % 3) * 64,
                           b2, ch + 2, tid);
        cp_commit();           // always commit to keep group cadence

        // ---- hoisted out1 writeout: cacc/dacc final after region D (ch 27);
        //      overlaps the remaining 8 region-B chunks. v0 even -> whole
        //      6-float group 8B-aligned -> 3 packed v2 REDs. ----
        if (ch == 28) {
#pragma unroll
            for (int r = 0; r < 2; r++) {
                const int er = r ? er1 : er0;
                if (eBase + er < E) {
                    const int node = dst_s[er];
                    const float s1v = sh1_s[er * 3 + 0];
                    const float s2v = sh1_s[er * 3 + 1];
                    const float s3v = sh1_s[er * 3 + 2];
#pragma unroll
                    for (int p = 0; p < 2; p++) {
                        const int v0 = p * 8 + 2 * qd;          // always even
                        float* base0 = &g_sums[node * 80 + 32 + v0 * 3];
                        const float cc0 = cacc[r][p][0];
                        const float cc1 = cacc[r][p][1];
                        red_add2(base0,
                                 NORM_V * (s1v * cc0 + dacc[r][p][0][0]),
                                 NORM_V * (s2v * cc0 + dacc[r][p][0][1]));
                        red_add2(base0 + 2,
                                 NORM_V * (s3v * cc0 + dacc[r][p][0][2]),
                                 NORM_V * (s1v * cc1 + dacc[r][p][1][0]));
                        red_add2(base0 + 4,
                                 NORM_V * (s2v * cc1 + dacc[r][p][1][1]),
                                 NORM_V * (s3v * cc1 + dacc[r][p][1][2]));
                    }
                }
            }
        }

        const unsigned chunk_b = wst_b + (unsigned)(((ch + 1) % 3) * 8192);
        const float*   bb      = b2st + ((ch + 1) % 3) * 64;

#pragma unroll
        for (int h2 = 0; h2 < 2; h2++) {
            float c[4][4];
#pragma unroll
            for (int n = 0; n < 4; n++) {
                const float bb0 = bb[(h2 * 4 + n) * 8 + 2 * qd];
                const float bb1 = bb[(h2 * 4 + n) * 8 + 2 * qd + 1];
                c[n][0] = bb0; c[n][1] = bb1; c[n][2] = bb0; c[n][3] = bb1;
            }
#pragma unroll
            for (int n = 0; n < 4; n++) {
                const unsigned nb_base = chunk_b + (unsigned)((h2 * 4 + n) * 1024);
                unsigned b0, b1r, b2r, b3, b4, b5, b6, b7;
                ldsm_x4(b0, b1r, b2r, b3, nb_base + lmoff0);   // ksegs 0..3
                ldsm_x4(b4, b5, b6,  b7, nb_base + lmoff1);    // ksegs 4..7
                mma_f16(c[n], a[0], b0, b1r);
                mma_f16(c[n], a[1], b2r, b3);
                mma_f16(c[n], a[2], b4, b5);
                mma_f16(c[n], a[3], b6, b7);
            }

            // region-aware contraction
            if (ch < 16) {                      // A (wa): u = 2ch + h2
#pragma unroll
                for (int r = 0; r < 2; r++) {
                    const int er = r ? er1 : er0;
                    const float y = x0_s[er * 33 + 2 * ch + h2] * sh0_s[er];
#pragma unroll
                    for (int n = 0; n < 4; n++) {
                        acc0[r][n][0] = fmaf(c[n][r * 2 + 0], y, acc0[r][n][0]);
                        acc0[r][n][1] = fmaf(c[n][r * 2 + 1], y, acc0[r][n][1]);
                    }
                }
            } else if (ch < 24) {               // C (wc): u = 4ch' + 2h2 + {0,1}
                const int chp = ch - 16;
#pragma unroll
                for (int r = 0; r < 2; r++) {
                    const int er = r ? er1 : er0;
                    const float xa = x0_s[er * 33 + 4 * chp + h2 * 2 + 0];
                    const float xb = x0_s[er * 33 + 4 * chp + h2 * 2 + 1];
#pragma unroll
                    for (int p = 0; p < 2; p++) {
                        cacc[r][p][0] = fmaf(c[p][r * 2 + 0], xa,
                                        fmaf(c[2 + p][r * 2 + 0], xb, cacc[r][p][0]));
                        cacc[r][p][1] = fmaf(c[p][r * 2 + 1], xa,
                                        fmaf(c[2 + p][r * 2 + 1], xb, cacc[r][p][1]));
                    }
                }
            } else if (ch < 28) {               // D (wd): u = 4ch' + 2h2 + t
                const int chp = ch - 24;
#pragma unroll
                for (int r = 0; r < 2; r++) {
                    const int er = r ? er1 : er0;
#pragma unroll
                    for (int t = 0; t < 2; t++) {
                        const int u = 4 * chp + h2 * 2 + t;
                        const float za = z1_s[er * 49 + u * 3 + 0];
                        const float zb = z1_s[er * 49 + u * 3 + 1];
                        const float zc = z1_s[er * 49 + u * 3 + 2];
#pragma unroll
                        for (int p = 0; p < 2; p++) {
                            const int n = t * 2 + p;
#pragma unroll
                            for (int j = 0; j < 2; j++) {
                                const float wv = c[n][r * 2 + j];
                                dacc[r][p][j][0] = fmaf(wv, za, dacc[r][p][j][0]);
                                dacc[r][p][j][1] = fmaf(wv, zb, dacc[r][p][j][1]);
                                dacc[r][p][j][2] = fmaf(wv, zc, dacc[r][p][j][2]);
                            }
                        }
                    }
                }
            } else {                            // B (wb): u = 2ch' + h2
                const int chp = ch - 28;
#pragma unroll
                for (int r = 0; r < 2; r++) {
                    const int er = r ? er1 : er0;
                    const float y = y1_s[er * 17 + 2 * chp + h2];
#pragma unroll
                    for (int n = 0; n < 4; n++) {
                        acc0[r][n][0] = fmaf(c[n][r * 2 + 0], y, acc0[r][n][0]);
                        acc0[r][n][1] = fmaf(c[n][r * 2 + 1], y, acc0[r][n][1]);
                    }
                }
            }
        }
    }

    // ---- out0 writeout (cols 0..31, packed pairs) + count ----
#pragma unroll
    for (int r = 0; r < 2; r++) {
        const int er = r ? er1 : er0;
        if (eBase + er < E) {
            const int node = dst_s[er];
#pragma unroll
            for (int n = 0; n < 4; n++) {
                const int col = n * 8 + 2 * qd;       // even -> 8B aligned
                red_add2(&g_sums[node * 80 + col],
                         NORM_V * acc0[r][n][0], NORM_V * acc0[r][n][1]);
            }
            if (qd == 0) red_add1(&g_cnt[node], 1.0f);
        }
    }
}

// ---------------------------------------------------------------------------
// residual + mean; restores g_sums/g_cnt to zero (graph-replay safe).
// 320 threads = 4 nodes/block; rw0/rw1 staged in smem; one rcp per node.
// ---------------------------------------------------------------------------
__global__ __launch_bounds__(320) void final_kernel(
    int n_nodes,
    const float* __restrict__ x_dst,
    const float* __restrict__ rw0,
    const float* __restrict__ rw1,
    float* __restrict__ out)
{
    __shared__ float w0s[1024];
    __shared__ float w1s[256];
    __shared__ float cs[4];
    const int tid = threadIdx.x;

    for (int i = tid; i < 1024; i += 320) w0s[i] = rw0[i];
    if (tid < 256) w1s[tid] = rw1[tid];

    const int local = tid / 80;
    const int j     = tid - local * 80;
    const int n     = blockIdx.x * 4 + local;
    const bool ok   = (n < n_nodes);

    if (ok && j == 0) cs[local] = 1.0f / fmaxf(g_cnt[n], 1.0f);
    __syncthreads();
    if (!ok) return;

    float res;
    if (j < 32) {
        float acc = 0.f;
#pragma unroll
        for (int u = 0; u < 32; u++)
            acc = fmaf(x_dst[n * 80 + u], w0s[u * 32 + j], acc);
        res = acc * RSQRT32_V;
    } else {
        const int w = (j - 32) / 3;
        const int m = (j - 32) - 3 * w;
        float acc = 0.f;
#pragma unroll
        for (int u = 0; u < 16; u++)
            acc = fmaf(x_dst[n * 80 + 32 + u * 3 + m], w1s[u * 16 + w], acc);
        res = acc * 0.25f;
    }
    const int idx = n * 80 + j;
    out[idx] = fmaf(g_sums[idx], cs[local], res);

    // restore zeros for next replay
    g_sums[idx] = 0.0f;
    if (j == 0) g_cnt[n] = 0.0f;
}

// ---------------------------------------------------------------------------
extern "C" void kernel_launch(void* const* d_in, const int* in_sizes, int n_in,
                              void* d_out, int out_size)
{
    const int*   dst       = (const int*)  d_in[0];
    const float* x_src     = (const float*)d_in[1];
    const float* x_dst     = (const float*)d_in[2];
    const float* sh        = (const float*)d_in[3];
    const float* edge_attr = (const float*)d_in[4];
    const float* w1        = (const float*)d_in[5];
    const float* b1        = (const float*)d_in[6];
    const float* w2        = (const float*)d_in[7];
    const float* b2        = (const float*)d_in[8];
    const float* rw0       = (const float*)d_in[9];
    const float* rw1       = (const float*)d_in[10];
    float* out = (float*)d_out;

    const int E       = in_sizes[0];
    const int n_nodes = in_sizes[2] / OUT_DIM;

    cudaFuncSetAttribute(edge_kernel,
                         cudaFuncAttributeMaxDynamicSharedMemorySize,
                         SMEM_BYTES);

    dim3 cblk(32, 8);
    convert_w2<<<72, cblk>>>(w2);
    edge_kernel<<<(E + 63) / 64, 128, SMEM_BYTES>>>(
        E, dst, x_src, sh, edge_attr, w1, b1, b2);
    final_kernel<<<(n_nodes + 3) / 4, 320>>>(
        n_nodes, x_dst, rw0, rw1, out);
}